// round 1
// baseline (speedup 1.0000x reference)
#include <cuda_runtime.h>
#include <math.h>

#define NN 4096
#define GG 1024
#define HH1 512
#define HH2 64
#define NHEAD 4
#define CHAN 128
#define SEDIM 16
#define CAP 256

// ---------------- scratch (static device globals; no allocation) ----------
__device__ float g_Hpre[NN * HH1];
__device__ float g_Hagg[NN * HH1];
__device__ float g_Bcat[GG * HH1];    // packed concat weights (max 1024x512)
__device__ float g_bcat[HH1];
__device__ float g_f1[NHEAD * NN];
__device__ float g_f2[NHEAD * NN];
__device__ float g_Hd[NN * (HH2 + SEDIM)];
__device__ int   g_cols[NN * CAP];
__device__ int   g_cnt[NN];

// ---------------- CSR build from dense adjacency ---------------------------
__global__ void build_csr(const float* __restrict__ adj) {
    int row = blockIdx.x;
    __shared__ int cnt;
    if (threadIdx.x == 0) cnt = 0;
    __syncthreads();
    const float4* arow = (const float4*)(adj + (size_t)row * NN);
    for (int j4 = threadIdx.x; j4 < NN / 4; j4 += blockDim.x) {
        float4 v = arow[j4];
        if (v.x != 0.f) { int k = atomicAdd(&cnt, 1); if (k < CAP) g_cols[row * CAP + k] = j4 * 4 + 0; }
        if (v.y != 0.f) { int k = atomicAdd(&cnt, 1); if (k < CAP) g_cols[row * CAP + k] = j4 * 4 + 1; }
        if (v.z != 0.f) { int k = atomicAdd(&cnt, 1); if (k < CAP) g_cols[row * CAP + k] = j4 * 4 + 2; }
        if (v.w != 0.f) { int k = atomicAdd(&cnt, 1); if (k < CAP) g_cols[row * CAP + k] = j4 * 4 + 3; }
    }
    __syncthreads();
    if (threadIdx.x == 0) g_cnt[row] = min(cnt, CAP);
}

// ---------------- pack [NH,K,CH] head weights into [K, NH*CH] --------------
__global__ void pack_w(const float* __restrict__ W, const float* __restrict__ b, int K) {
    int idx = blockIdx.x * blockDim.x + threadIdx.x;
    if (idx < K * HH1) {
        int k = idx / HH1;
        int j = idx % HH1;
        int h = j / CHAN, c = j % CHAN;
        g_Bcat[idx] = W[((size_t)h * K + k) * CHAN + c];
    }
    if (idx < HH1) {
        int h = idx / CHAN, c = idx % CHAN;
        g_bcat[idx] = b[h * CHAN + c];
    }
}

// ---------------- fp32 GEMM, 128x128 tiles, 8x8 per thread -----------------
// C[M,Nc] = A[M,K] @ B[K,Nc] + bias[Nc].  Requires M%128==0, Nc%128==0, K%16==0, K%4==0.
__global__ __launch_bounds__(256) void gemm128(const float* __restrict__ A,
                                               const float* __restrict__ B,
                                               const float* __restrict__ bias,
                                               float* __restrict__ C,
                                               int M, int K, int Nc) {
    __shared__ float As[16][128];
    __shared__ float Bs[16][128];
    int tid = threadIdx.x;
    int tx = tid % 16, ty = tid / 16;
    int m0 = blockIdx.y * 128, n0 = blockIdx.x * 128;
    float acc[8][8];
#pragma unroll
    for (int i = 0; i < 8; i++)
#pragma unroll
        for (int j = 0; j < 8; j++) acc[i][j] = 0.f;

    for (int k0 = 0; k0 < K; k0 += 16) {
#pragma unroll
        for (int i = 0; i < 2; i++) {
            int r = tid / 4 + i * 64;
            int c = (tid % 4) * 4;
            float4 a = *(const float4*)(A + (size_t)(m0 + r) * K + k0 + c);
            As[c + 0][r] = a.x; As[c + 1][r] = a.y; As[c + 2][r] = a.z; As[c + 3][r] = a.w;
        }
#pragma unroll
        for (int i = 0; i < 2; i++) {
            int r = tid / 32 + i * 8;
            int c = (tid % 32) * 4;
            *(float4*)(&Bs[r][c]) = *(const float4*)(B + (size_t)(k0 + r) * Nc + n0 + c);
        }
        __syncthreads();
#pragma unroll
        for (int k = 0; k < 16; k++) {
            float4 a0 = *(const float4*)(&As[k][ty * 8]);
            float4 a1 = *(const float4*)(&As[k][ty * 8 + 4]);
            float4 b0 = *(const float4*)(&Bs[k][tx * 8]);
            float4 b1 = *(const float4*)(&Bs[k][tx * 8 + 4]);
            float av[8] = {a0.x, a0.y, a0.z, a0.w, a1.x, a1.y, a1.z, a1.w};
            float bv[8] = {b0.x, b0.y, b0.z, b0.w, b1.x, b1.y, b1.z, b1.w};
#pragma unroll
            for (int i = 0; i < 8; i++)
#pragma unroll
                for (int j = 0; j < 8; j++) acc[i][j] += av[i] * bv[j];
        }
        __syncthreads();
    }
#pragma unroll
    for (int i = 0; i < 8; i++) {
        int m = m0 + ty * 8 + i;
#pragma unroll
        for (int j = 0; j < 8; j++) {
            int n = n0 + tx * 8 + j;
            C[(size_t)m * Nc + n] = acc[i][j] + bias[n];
        }
    }
}

// ---------------- fp32 GEMM, 64x64 tiles, 4x4 per thread -------------------
__global__ __launch_bounds__(256) void gemm64(const float* __restrict__ A,
                                              const float* __restrict__ B,
                                              const float* __restrict__ bias,
                                              float* __restrict__ C,
                                              int M, int K, int Nc) {
    __shared__ float As[16][64];
    __shared__ float Bs[16][64];
    int tid = threadIdx.x;
    int tx = tid % 16, ty = tid / 16;
    int m0 = blockIdx.y * 64, n0 = blockIdx.x * 64;
    float acc[4][4];
#pragma unroll
    for (int i = 0; i < 4; i++)
#pragma unroll
        for (int j = 0; j < 4; j++) acc[i][j] = 0.f;

    for (int k0 = 0; k0 < K; k0 += 16) {
        {
            int r = tid / 4;
            int c = (tid % 4) * 4;
            float4 a = *(const float4*)(A + (size_t)(m0 + r) * K + k0 + c);
            As[c + 0][r] = a.x; As[c + 1][r] = a.y; As[c + 2][r] = a.z; As[c + 3][r] = a.w;
        }
        {
            int r = tid / 16;
            int c = (tid % 16) * 4;
            *(float4*)(&Bs[r][c]) = *(const float4*)(B + (size_t)(k0 + r) * Nc + n0 + c);
        }
        __syncthreads();
#pragma unroll
        for (int k = 0; k < 16; k++) {
            float4 a4 = *(const float4*)(&As[k][ty * 4]);
            float4 b4 = *(const float4*)(&Bs[k][tx * 4]);
            float av[4] = {a4.x, a4.y, a4.z, a4.w};
            float bv[4] = {b4.x, b4.y, b4.z, b4.w};
#pragma unroll
            for (int i = 0; i < 4; i++)
#pragma unroll
                for (int j = 0; j < 4; j++) acc[i][j] += av[i] * bv[j];
        }
        __syncthreads();
    }
#pragma unroll
    for (int i = 0; i < 4; i++) {
        int m = m0 + ty * 4 + i;
#pragma unroll
        for (int j = 0; j < 4; j++) {
            int n = n0 + tx * 4 + j;
            C[(size_t)m * Nc + n] = acc[i][j] + bias[n];
        }
    }
}

// ---------------- attention features f1 = h@v0, f2 = h@v1 ------------------
__global__ void feats(const float* __restrict__ Hpre,
                      const float* __restrict__ v0,
                      const float* __restrict__ v1) {
    int n = blockIdx.x;
    int w = threadIdx.x / 32;   // head
    int l = threadIdx.x % 32;
    float4 hv = *(const float4*)(Hpre + (size_t)n * HH1 + w * CHAN + l * 4);
    float4 a  = *(const float4*)(v0 + w * CHAN + l * 4);
    float4 b  = *(const float4*)(v1 + w * CHAN + l * 4);
    float s1 = hv.x * a.x + hv.y * a.y + hv.z * a.z + hv.w * a.w;
    float s2 = hv.x * b.x + hv.y * b.y + hv.z * b.z + hv.w * b.w;
#pragma unroll
    for (int o = 16; o > 0; o >>= 1) {
        s1 += __shfl_down_sync(0xffffffffu, s1, o);
        s2 += __shfl_down_sync(0xffffffffu, s2, o);
    }
    if (l == 0) {
        g_f1[w * NN + n] = s1;
        g_f2[w * NN + n] = s2;
    }
}

// ---------------- sparse attention softmax + aggregation + ELU -------------
__global__ __launch_bounds__(128) void gat_agg(const float* __restrict__ Hpre,
                                               float* __restrict__ out) {
    int row = blockIdx.x, h = blockIdx.y, t = threadIdx.x;
    int cnt = g_cnt[row];
    __shared__ float sw[CAP];
    __shared__ int   sc[CAP];
    __shared__ float red[128];
    __shared__ float s_mx, s_inv;

    float f1r = g_f1[h * NN + row];
    float localmax = -1e30f;
    for (int k = t; k < cnt; k += 128) {
        int col = g_cols[row * CAP + k];
        float x = f1r + g_f2[h * NN + col];
        float u = 1.f / (1.f + __expf(-x)) - 0.5f;  // see note: use precise expf
        u = 1.f / (1.f + expf(-x)) - 0.5f;
        sc[k] = col;
        sw[k] = u;
        if (u != 0.f) localmax = fmaxf(localmax, u);
    }
    red[t] = localmax;
    __syncthreads();
#pragma unroll
    for (int s = 64; s > 0; s >>= 1) {
        if (t < s) red[t] = fmaxf(red[t], red[t + s]);
        __syncthreads();
    }
    if (t == 0) s_mx = red[0];
    __syncthreads();
    float mx = s_mx;

    float localsum = 0.f;
    for (int k = t; k < cnt; k += 128) {
        float u = sw[k];
        float e = (u != 0.f) ? expf(u - mx) : 0.f;
        sw[k] = e;
        localsum += e;
    }
    red[t] = localsum;
    __syncthreads();
#pragma unroll
    for (int s = 64; s > 0; s >>= 1) {
        if (t < s) red[t] += red[t + s];
        __syncthreads();
    }
    if (t == 0) s_inv = 1.f / fmaxf(red[0], 1e-30f);
    __syncthreads();
    float inv = s_inv;

    // each thread owns one channel c = t of this head
    float acc = 0.f;
    const float* Hh = Hpre + h * CHAN + t;
    for (int k = 0; k < cnt; k++) {
        acc += sw[k] * Hh[(size_t)sc[k] * HH1];
    }
    acc *= inv;
    out[(size_t)row * HH1 + h * CHAN + t] = (acc > 0.f) ? acc : expm1f(acc);
}

// ---------------- Hd = concat(Z, emb[slice]) -------------------------------
__global__ void build_hd(const float* __restrict__ Z,
                         const int* __restrict__ slice,
                         const float* __restrict__ emb) {
    int n = blockIdx.x, t = threadIdx.x;  // 80 threads
    float v;
    if (t < HH2) v = Z[(size_t)n * HH2 + t];
    else         v = emb[slice[n] * SEDIM + (t - HH2)];
    g_Hd[(size_t)n * (HH2 + SEDIM) + t] = v;
}

extern "C" void kernel_launch(void* const* d_in, const int* in_sizes, int n_in,
                              void* d_out, int out_size) {
    const float* adj       = (const float*)d_in[0];
    const float* node      = (const float*)d_in[1];
    const int*   slice     = (const int*)d_in[4];
    const float* enc1_W    = (const float*)d_in[6];
    const float* enc1_b    = (const float*)d_in[7];
    const float* enc1_v0   = (const float*)d_in[8];
    const float* enc1_v1   = (const float*)d_in[9];
    const float* enc2_W    = (const float*)d_in[10];
    const float* enc2_b    = (const float*)d_in[11];
    const float* dec1_W    = (const float*)d_in[12];
    const float* dec1_b    = (const float*)d_in[13];
    const float* dec1_v0   = (const float*)d_in[14];
    const float* dec1_v1   = (const float*)d_in[15];
    const float* dec2_W    = (const float*)d_in[16];
    const float* dec2_b    = (const float*)d_in[17];
    const float* emb       = (const float*)d_in[18];

    float* out_recon = (float*)d_out;                       // [N, G]
    float* out_Z     = (float*)d_out + (size_t)NN * GG;     // [N, H2]

    float* Hpre; cudaGetSymbolAddress((void**)&Hpre, g_Hpre);
    float* Hagg; cudaGetSymbolAddress((void**)&Hagg, g_Hagg);
    float* Bcat; cudaGetSymbolAddress((void**)&Bcat, g_Bcat);
    float* bcat; cudaGetSymbolAddress((void**)&bcat, g_bcat);
    float* Hd;   cudaGetSymbolAddress((void**)&Hd, g_Hd);

    // 1. dense adj -> per-row column lists
    build_csr<<<NN, 256>>>(adj);

    // 2. encoder GAT layer 1
    pack_w<<<(GG * HH1 + 255) / 256, 256>>>(enc1_W, enc1_b, GG);
    gemm128<<<dim3(HH1 / 128, NN / 128), 256>>>(node, Bcat, bcat, Hpre, NN, GG, HH1);
    feats<<<NN, 128>>>(Hpre, enc1_v0, enc1_v1);
    gat_agg<<<dim3(NN, NHEAD), 128>>>(Hpre, Hagg);

    // 3. Z = Hagg @ enc2_W + b   (written straight to output tail)
    gemm64<<<dim3(HH2 / 64, NN / 64), 256>>>(Hagg, enc2_W, enc2_b, out_Z, NN, HH1, HH2);

    // 4. decoder GAT layer
    build_hd<<<NN, HH2 + SEDIM>>>(out_Z, slice, emb);
    pack_w<<<((HH2 + SEDIM) * HH1 + 255) / 256, 256>>>(dec1_W, dec1_b, HH2 + SEDIM);
    gemm128<<<dim3(HH1 / 128, NN / 128), 256>>>(Hd, Bcat, bcat, Hpre, NN, HH2 + SEDIM, HH1);
    feats<<<NN, 128>>>(Hpre, dec1_v0, dec1_v1);
    gat_agg<<<dim3(NN, NHEAD), 128>>>(Hpre, Hagg);

    // 5. recon = Hagg @ dec2_W + b
    gemm128<<<dim3(GG / 128, NN / 128), 256>>>(Hagg, dec2_W, dec2_b, out_recon, NN, HH1, GG);
}

// round 3
// speedup vs baseline: 1.7201x; 1.7201x over previous
#include <cuda_runtime.h>
#include <cuda_bf16.h>
#include <math.h>
#include <stdint.h>

#define NN 4096
#define GG 1024
#define HH1 512
#define HH2 64
#define NHEAD 4
#define CHAN 128
#define SEDIM 16
#define CAP 256
#define KP_DEC 128

// ---------------- scratch (static device globals; no allocation) ----------
__device__ __nv_bfloat16 g_Ahi[NN * GG];   // activation hi (bf16 split)
__device__ __nv_bfloat16 g_Alo[NN * GG];   // activation lo
__device__ __nv_bfloat16 g_Bhi[GG * HH1];  // weight hi, [n][k] K-major
__device__ __nv_bfloat16 g_Blo[GG * HH1];
__device__ float g_Hpre[NN * HH1];
__device__ float g_f1[NHEAD * NN];
__device__ float g_f2[NHEAD * NN];
__device__ int   g_cols[NN * CAP];
__device__ int   g_cnt[NN];

// ---------------- helpers ---------------------------------------------------
__device__ __forceinline__ void bsplit(float x, __nv_bfloat16* h, __nv_bfloat16* l) {
    __nv_bfloat16 hh = __float2bfloat16_rn(x);
    *h = hh;
    *l = __float2bfloat16_rn(x - __bfloat162float(hh));
}
__device__ __forceinline__ uint32_t smem_u32(const void* p) {
    uint32_t a;
    asm("{ .reg .u64 t; cvta.to.shared.u64 t, %1; cvt.u32.u64 %0, t; }" : "=r"(a) : "l"(p));
    return a;
}
#define LDM4(r, addr) \
    asm volatile("ldmatrix.sync.aligned.m8n8.x4.shared.b16 {%0,%1,%2,%3}, [%4];" \
                 : "=r"((r)[0]), "=r"((r)[1]), "=r"((r)[2]), "=r"((r)[3]) : "r"(addr))
#define MMA16816(d, a, b0_, b1_) \
    asm volatile("mma.sync.aligned.m16n8k16.row.col.f32.bf16.bf16.f32 " \
                 "{%0,%1,%2,%3}, {%4,%5,%6,%7}, {%8,%9}, {%0,%1,%2,%3};" \
                 : "+f"((d)[0]), "+f"((d)[1]), "+f"((d)[2]), "+f"((d)[3]) \
                 : "r"((a)[0]), "r"((a)[1]), "r"((a)[2]), "r"((a)[3]), "r"(b0_), "r"(b1_))

// ---------------- CSR build from dense adjacency ---------------------------
__global__ void build_csr(const float* __restrict__ adj) {
    int row = blockIdx.x;
    __shared__ int cnt;
    if (threadIdx.x == 0) cnt = 0;
    __syncthreads();
    const float4* arow = (const float4*)(adj + (size_t)row * NN);
    for (int j4 = threadIdx.x; j4 < NN / 4; j4 += blockDim.x) {
        float4 v = arow[j4];
        if (v.x != 0.f) { int k = atomicAdd(&cnt, 1); if (k < CAP) g_cols[row * CAP + k] = j4 * 4 + 0; }
        if (v.y != 0.f) { int k = atomicAdd(&cnt, 1); if (k < CAP) g_cols[row * CAP + k] = j4 * 4 + 1; }
        if (v.z != 0.f) { int k = atomicAdd(&cnt, 1); if (k < CAP) g_cols[row * CAP + k] = j4 * 4 + 2; }
        if (v.w != 0.f) { int k = atomicAdd(&cnt, 1); if (k < CAP) g_cols[row * CAP + k] = j4 * 4 + 3; }
    }
    __syncthreads();
    if (threadIdx.x == 0) g_cnt[row] = min(cnt, CAP);
}

// ---------------- split node feats into bf16 hi/lo --------------------------
__global__ void cvt_node(const float4* __restrict__ x) {
    int i = blockIdx.x * blockDim.x + threadIdx.x;  // over NN*GG/4
    float4 v = x[i];
    int b = i * 4;
    bsplit(v.x, &g_Ahi[b + 0], &g_Alo[b + 0]);
    bsplit(v.y, &g_Ahi[b + 1], &g_Alo[b + 1]);
    bsplit(v.z, &g_Ahi[b + 2], &g_Alo[b + 2]);
    bsplit(v.w, &g_Ahi[b + 3], &g_Alo[b + 3]);
}

// ---------------- pack [NH,K,CH] head weights -> B[n=512][KPad] + split -----
__global__ void pack_headsB(const float* __restrict__ W, int K, int KPad) {
    int idx = blockIdx.x * blockDim.x + threadIdx.x;
    if (idx >= HH1 * KPad) return;
    int n = idx / KPad, k = idx - n * KPad;
    int h = n >> 7, c = n & 127;
    float v = (k < K) ? W[((size_t)h * K + k) * CHAN + c] : 0.f;
    bsplit(v, &g_Bhi[idx], &g_Blo[idx]);
}

// ---------------- transpose W[K,Nc] -> B[Nc][K] + split ---------------------
__global__ void pack_tB(const float* __restrict__ W, int K, int Nc) {
    int idx = blockIdx.x * blockDim.x + threadIdx.x;
    if (idx >= K * Nc) return;
    int k = idx / Nc, n = idx - k * Nc;
    bsplit(W[idx], &g_Bhi[(size_t)n * K + k], &g_Blo[(size_t)n * K + k]);
}

// ---------------- HMMA bf16-split GEMM, 128 x NT tiles ----------------------
// C[4096,Nc] = (Ahi+Alo)[4096,K] @ (Bhi+Blo)[Nc,K]^T + bias.  K % 32 == 0.
template <int NT>
__global__ void __launch_bounds__(256)
gemm_hmma(const float* __restrict__ bias, float* __restrict__ C, int K, int Nc) {
    constexpr int WMW = (NT == 128) ? 2 : 4;      // warps along m
    constexpr int WNW = 8 / WMW;                  // warps along n
    constexpr int WM  = 128 / WMW;                // 64 or 32
    constexpr int WN  = NT / WNW;                 // 32
    constexpr int MT  = WM / 16;                  // 4 or 2
    constexpr int NTL = WN / 8;                   // 4
    constexpr int NP  = NTL / 2;                  // 2
    constexpr int ASZ = 128 * 80;                 // bytes per A tile (stride 40 bf16)
    constexpr int BSZ = NT * 80;
    constexpr int STG = 2 * ASZ + 2 * BSZ;
    constexpr int BJ  = NT / 64;                  // uint4 per thread per B array

    extern __shared__ char sm[];
    const int tid = threadIdx.x, lane = tid & 31, wid = tid >> 5;
    const int m0 = blockIdx.y * 128, n0 = blockIdx.x * NT;
    const int wm0 = (wid % WMW) * WM, wn0 = (wid / WMW) * WN;

    // global load mapping (A: 128 rows x 32 bf16, 2 threads/row)
    const int ar = tid >> 1, ac = (tid & 1) * 16;
    const size_t abase = (size_t)(m0 + ar) * K + ac;
    const int br = (BJ == 2) ? (tid >> 1) : (tid >> 2);
    const int bc = (BJ == 2) ? ((tid & 1) * 16) : ((tid & 3) * 8);
    const size_t bbase = (size_t)(n0 + br) * K + bc;

    const uint32_t sA = smem_u32(sm);
    const uint32_t stA = ar * 80 + ac * 2;
    const uint32_t stB = br * 80 + bc * 2;

    const int lr = lane & 15, lk = (lane >> 4) * 8;
    const uint32_t aoff = (wm0 + lr) * 80 + lk * 2;
    const uint32_t boff = (wn0 + lr) * 80 + lk * 2;

    float acc[MT][NTL][4];
#pragma unroll
    for (int i = 0; i < MT; i++)
#pragma unroll
        for (int j = 0; j < NTL; j++)
#pragma unroll
            for (int q = 0; q < 4; q++) acc[i][j][q] = 0.f;

    const int NC = K >> 5;
    uint4 pAh[2], pAl[2], pBh[BJ], pBl[BJ];

#define GLOAD(c0)                                                              \
    {                                                                          \
        int k0 = (c0) * 32;                                                    \
        _Pragma("unroll") for (int j = 0; j < 2; j++) {                        \
            pAh[j] = *(const uint4*)(g_Ahi + abase + k0 + j * 8);              \
            pAl[j] = *(const uint4*)(g_Alo + abase + k0 + j * 8);              \
        }                                                                      \
        _Pragma("unroll") for (int j = 0; j < BJ; j++) {                       \
            pBh[j] = *(const uint4*)(g_Bhi + bbase + k0 + j * 8);              \
            pBl[j] = *(const uint4*)(g_Blo + bbase + k0 + j * 8);              \
        }                                                                      \
    }
#define SSTORE(buf)                                                            \
    {                                                                          \
        char* p = sm + (buf) * STG;                                            \
        _Pragma("unroll") for (int j = 0; j < 2; j++) {                        \
            *(uint4*)(p + stA + j * 16) = pAh[j];                              \
            *(uint4*)(p + ASZ + stA + j * 16) = pAl[j];                        \
        }                                                                      \
        _Pragma("unroll") for (int j = 0; j < BJ; j++) {                       \
            *(uint4*)(p + 2 * ASZ + stB + j * 16) = pBh[j];                    \
            *(uint4*)(p + 2 * ASZ + BSZ + stB + j * 16) = pBl[j];              \
        }                                                                      \
    }

    GLOAD(0);
    SSTORE(0);
    for (int c = 0; c < NC; c++) {
        __syncthreads();
        if (c + 1 < NC) GLOAD(c + 1);
        uint32_t uAh = sA + (c & 1) * STG;
        uint32_t uAl = uAh + ASZ;
        uint32_t uBh = uAh + 2 * ASZ;
        uint32_t uBl = uBh + BSZ;
#pragma unroll
        for (int ks = 0; ks < 2; ks++) {
            uint32_t ah[MT][4], al[MT][4], bh[NP][4], bl[NP][4];
#pragma unroll
            for (int mt = 0; mt < MT; mt++) LDM4(ah[mt], uAh + aoff + mt * 1280 + ks * 32);
#pragma unroll
            for (int mt = 0; mt < MT; mt++) LDM4(al[mt], uAl + aoff + mt * 1280 + ks * 32);
#pragma unroll
            for (int p = 0; p < NP; p++) LDM4(bh[p], uBh + boff + p * 1280 + ks * 32);
#pragma unroll
            for (int p = 0; p < NP; p++) LDM4(bl[p], uBl + boff + p * 1280 + ks * 32);
            // term 1: hi*hi
#pragma unroll
            for (int mt = 0; mt < MT; mt++)
#pragma unroll
                for (int p = 0; p < NP; p++) {
                    MMA16816(acc[mt][2 * p],     ah[mt], bh[p][0], bh[p][2]);
                    MMA16816(acc[mt][2 * p + 1], ah[mt], bh[p][1], bh[p][3]);
                }
            // term 2: hi*lo
#pragma unroll
            for (int mt = 0; mt < MT; mt++)
#pragma unroll
                for (int p = 0; p < NP; p++) {
                    MMA16816(acc[mt][2 * p],     ah[mt], bl[p][0], bl[p][2]);
                    MMA16816(acc[mt][2 * p + 1], ah[mt], bl[p][1], bl[p][3]);
                }
            // term 3: lo*hi
#pragma unroll
            for (int mt = 0; mt < MT; mt++)
#pragma unroll
                for (int p = 0; p < NP; p++) {
                    MMA16816(acc[mt][2 * p],     al[mt], bh[p][0], bh[p][2]);
                    MMA16816(acc[mt][2 * p + 1], al[mt], bh[p][1], bh[p][3]);
                }
        }
        if (c + 1 < NC) SSTORE((c + 1) & 1);
    }

    // epilogue: bias + store
    int g = lane >> 2, tg = lane & 3;
#pragma unroll
    for (int mt = 0; mt < MT; mt++) {
        int row = m0 + wm0 + mt * 16 + g;
#pragma unroll
        for (int nt = 0; nt < NTL; nt++) {
            int col = n0 + wn0 + nt * 8 + tg * 2;
            float b0 = bias[col], b1 = bias[col + 1];
            C[(size_t)row * Nc + col]           = acc[mt][nt][0] + b0;
            C[(size_t)row * Nc + col + 1]       = acc[mt][nt][1] + b1;
            C[(size_t)(row + 8) * Nc + col]     = acc[mt][nt][2] + b0;
            C[(size_t)(row + 8) * Nc + col + 1] = acc[mt][nt][3] + b1;
        }
    }
#undef GLOAD
#undef SSTORE
}

// ---------------- attention features f1 = h@v0, f2 = h@v1 ------------------
__global__ void feats(const float* __restrict__ Hpre,
                      const float* __restrict__ v0,
                      const float* __restrict__ v1) {
    int n = blockIdx.x;
    int w = threadIdx.x / 32;
    int l = threadIdx.x % 32;
    float4 hv = *(const float4*)(Hpre + (size_t)n * HH1 + w * CHAN + l * 4);
    float4 a  = *(const float4*)(v0 + w * CHAN + l * 4);
    float4 b  = *(const float4*)(v1 + w * CHAN + l * 4);
    float s1 = hv.x * a.x + hv.y * a.y + hv.z * a.z + hv.w * a.w;
    float s2 = hv.x * b.x + hv.y * b.y + hv.z * b.z + hv.w * b.w;
#pragma unroll
    for (int o = 16; o > 0; o >>= 1) {
        s1 += __shfl_down_sync(0xffffffffu, s1, o);
        s2 += __shfl_down_sync(0xffffffffu, s2, o);
    }
    if (l == 0) {
        g_f1[w * NN + n] = s1;
        g_f2[w * NN + n] = s2;
    }
}

// ---------------- sparse attention softmax + aggregation + ELU -------------
// block = one row, warp = one head; writes bf16 hi/lo split for next GEMM
__global__ void __launch_bounds__(128) gat_agg2(const float* __restrict__ Hpre) {
    int row = blockIdx.x, tid = threadIdx.x, wid = tid >> 5, lid = tid & 31;
    int cnt = g_cnt[row];
    __shared__ int sc[CAP];
    __shared__ float sw[NHEAD][CAP];
    for (int k = tid; k < cnt; k += 128) sc[k] = g_cols[row * CAP + k];
    __syncthreads();

    float f1r = g_f1[wid * NN + row];
    float mx = -1e30f;
    for (int k = lid; k < cnt; k += 32) {
        float x = f1r + g_f2[wid * NN + sc[k]];
        float u = 1.f / (1.f + expf(-x)) - 0.5f;
        sw[wid][k] = u;
        if (u != 0.f) mx = fmaxf(mx, u);
    }
#pragma unroll
    for (int o = 16; o; o >>= 1) mx = fmaxf(mx, __shfl_xor_sync(0xffffffffu, mx, o));
    __syncwarp();
    float s = 0.f;
    for (int k = lid; k < cnt; k += 32) {
        float u = sw[wid][k];
        float e = (u != 0.f) ? expf(u - mx) : 0.f;
        sw[wid][k] = e;
        s += e;
    }
#pragma unroll
    for (int o = 16; o; o >>= 1) s += __shfl_xor_sync(0xffffffffu, s, o);
    float inv = 1.f / fmaxf(s, 1e-30f);
    __syncwarp();

    float4 acc = {0.f, 0.f, 0.f, 0.f};
    const float* Hb = Hpre + wid * CHAN + lid * 4;
    for (int k = 0; k < cnt; k++) {
        float w = sw[wid][k];
        float4 hv = *(const float4*)(Hb + (size_t)sc[k] * HH1);
        acc.x += w * hv.x; acc.y += w * hv.y; acc.z += w * hv.z; acc.w += w * hv.w;
    }
    acc.x *= inv; acc.y *= inv; acc.z *= inv; acc.w *= inv;
    acc.x = (acc.x > 0.f) ? acc.x : expm1f(acc.x);
    acc.y = (acc.y > 0.f) ? acc.y : expm1f(acc.y);
    acc.z = (acc.z > 0.f) ? acc.z : expm1f(acc.z);
    acc.w = (acc.w > 0.f) ? acc.w : expm1f(acc.w);
    size_t base = (size_t)row * HH1 + wid * CHAN + lid * 4;
    bsplit(acc.x, &g_Ahi[base + 0], &g_Alo[base + 0]);
    bsplit(acc.y, &g_Ahi[base + 1], &g_Alo[base + 1]);
    bsplit(acc.z, &g_Ahi[base + 2], &g_Alo[base + 2]);
    bsplit(acc.w, &g_Ahi[base + 3], &g_Alo[base + 3]);
}

// ---------------- Hd = concat(Z, emb[slice], zero-pad to 128), split -------
__global__ void build_hd(const float* __restrict__ Z,
                         const int* __restrict__ slice,
                         const float* __restrict__ emb) {
    int n = blockIdx.x, t = threadIdx.x;  // 128 threads
    float v = 0.f;
    if (t < HH2) v = Z[(size_t)n * HH2 + t];
    else if (t < HH2 + SEDIM) v = emb[slice[n] * SEDIM + (t - HH2)];
    bsplit(v, &g_Ahi[(size_t)n * KP_DEC + t], &g_Alo[(size_t)n * KP_DEC + t]);
}

extern "C" void kernel_launch(void* const* d_in, const int* in_sizes, int n_in,
                              void* d_out, int out_size) {
    const float* adj     = (const float*)d_in[0];
    const float* node    = (const float*)d_in[1];
    const int*   slice   = (const int*)d_in[4];
    const float* enc1_W  = (const float*)d_in[6];
    const float* enc1_b  = (const float*)d_in[7];
    const float* enc1_v0 = (const float*)d_in[8];
    const float* enc1_v1 = (const float*)d_in[9];
    const float* enc2_W  = (const float*)d_in[10];
    const float* enc2_b  = (const float*)d_in[11];
    const float* dec1_W  = (const float*)d_in[12];
    const float* dec1_b  = (const float*)d_in[13];
    const float* dec1_v0 = (const float*)d_in[14];
    const float* dec1_v1 = (const float*)d_in[15];
    const float* dec2_W  = (const float*)d_in[16];
    const float* dec2_b  = (const float*)d_in[17];
    const float* emb     = (const float*)d_in[18];

    float* out_recon = (float*)d_out;                   // [N, G]
    float* out_Z     = (float*)d_out + (size_t)NN * GG; // [N, H2]

    float* Hpre; cudaGetSymbolAddress((void**)&Hpre, g_Hpre);

    const int SM128 = 2 * (2 * 128 * 80 + 2 * 128 * 80); // 81920
    const int SM64  = 2 * (2 * 128 * 80 + 2 * 64 * 80);  // 61440
    static int attr_done = 0;
    cudaFuncSetAttribute(gemm_hmma<128>, cudaFuncAttributeMaxDynamicSharedMemorySize, SM128);
    cudaFuncSetAttribute(gemm_hmma<64>,  cudaFuncAttributeMaxDynamicSharedMemorySize, SM64);
    (void)attr_done;

    // 1. dense adj -> per-row column lists
    build_csr<<<NN, 256>>>(adj);

    // 2. encoder GAT layer 1
    cvt_node<<<NN * GG / 4 / 256, 256>>>((const float4*)node);
    pack_headsB<<<(HH1 * GG + 255) / 256, 256>>>(enc1_W, GG, GG);
    gemm_hmma<128><<<dim3(HH1 / 128, NN / 128), 256, SM128>>>(enc1_b, Hpre, GG, HH1);
    feats<<<NN, 128>>>(Hpre, enc1_v0, enc1_v1);
    gat_agg2<<<NN, 128>>>(Hpre);   // -> g_Ahi/g_Alo [4096,512]

    // 3. Z = Hagg @ enc2_W + b  (straight to output tail)
    pack_tB<<<(HH1 * HH2 + 255) / 256, 256>>>(enc2_W, HH1, HH2);
    gemm_hmma<64><<<dim3(1, NN / 128), 256, SM64>>>(enc2_b, out_Z, HH1, HH2);

    // 4. decoder GAT layer (K padded 80 -> 128)
    build_hd<<<NN, 128>>>(out_Z, slice, emb);   // -> g_Ahi/g_Alo [4096,128]
    pack_headsB<<<(HH1 * KP_DEC + 255) / 256, 256>>>(dec1_W, HH2 + SEDIM, KP_DEC);
    gemm_hmma<128><<<dim3(HH1 / 128, NN / 128), 256, SM128>>>(dec1_b, Hpre, KP_DEC, HH1);
    feats<<<NN, 128>>>(Hpre, dec1_v0, dec1_v1);
    gat_agg2<<<NN, 128>>>(Hpre);   // -> g_Ahi/g_Alo [4096,512]

    // 5. recon = Hagg @ dec2_W + b
    pack_tB<<<(HH1 * GG + 255) / 256, 256>>>(dec2_W, HH1, GG);
    gemm_hmma<128><<<dim3(GG / 128, NN / 128), 256, SM128>>>(dec2_b, out_recon, HH1, GG);
}